// round 1
// baseline (speedup 1.0000x reference)
#include <cuda_runtime.h>
#include <cuda_bf16.h>
#include <mma.h>

using namespace nvcuda;

static constexpr int BATCH = 4;
static constexpr int NTOK  = 4096;   // H*W
static constexpr int CH    = 512;
static constexpr int FGD   = 64;

static constexpr long long O_ELEMS = (long long)BATCH * NTOK * CH;    // 8388608
static constexpr long long B_ELEMS = (long long)BATCH * NTOK * NTOK;  // 67108864

// ---------------- scratch (static __device__ -- no allocations allowed) ----------
__device__ float d_f[(size_t)BATCH * NTOK * FGD];
__device__ float d_g[(size_t)BATCH * NTOK * FGD];
__device__ float d_h[(size_t)BATCH * NTOK * CH];
__device__ float d_oatt[(size_t)BATCH * NTOK * CH];
__device__ float d_rowm[BATCH * NTOK];
__device__ float d_rowl[BATCH * NTOK];
__device__ float d_beta_scratch[(size_t)BATCH * NTOK * NTOK]; // used only if harness wants o-only

// ---------------- bf16 split helper (x = hi + lo, ~17-bit effective mantissa) ----
__device__ __forceinline__ void split4(const float4 v, __nv_bfloat16* hi, __nv_bfloat16* lo) {
    hi[0] = __float2bfloat16(v.x); lo[0] = __float2bfloat16(v.x - __bfloat162float(hi[0]));
    hi[1] = __float2bfloat16(v.y); lo[1] = __float2bfloat16(v.y - __bfloat162float(hi[1]));
    hi[2] = __float2bfloat16(v.z); lo[2] = __float2bfloat16(v.z - __bfloat162float(hi[2]));
    hi[3] = __float2bfloat16(v.w); lo[3] = __float2bfloat16(v.w - __bfloat162float(hi[3]));
}

// ================== generic GEMM: C = act(A[M,K] @ B[K,N] + bias) =================
// A, B, C fp32 row-major contiguous (lda=K, ldb=N, ldc=N).
// bf16-split 3-mma scheme for near-fp32 accuracy. M%128==0, N%64==0, K%32==0.
static constexpr int GBM = 128, GBN = 64, GBK = 32;
static constexpr int ALD = GBK + 8;   // 40 (bf16 elems; ld mult of 8 ok)
static constexpr int BLD = GBN + 8;   // 72
static constexpr int CLD = GBN + 4;   // 68
static constexpr int GEMM_SMEM_BYTES = 35840; // >= max(2*128*40*2 + 2*32*72*2, 128*68*4)

__global__ void __launch_bounds__(256)
gemm_split_kernel(const float* __restrict__ A, const float* __restrict__ B,
                  const float* __restrict__ bias, float* __restrict__ C,
                  int K, int N,
                  long long sA, long long sB, long long sC, int relu)
{
    __shared__ __align__(16) unsigned char smbuf[GEMM_SMEM_BYTES];
    __nv_bfloat16* Ahi = reinterpret_cast<__nv_bfloat16*>(smbuf);
    __nv_bfloat16* Alo = Ahi + GBM * ALD;
    __nv_bfloat16* Bhi = Alo + GBM * ALD;
    __nv_bfloat16* Blo = Bhi + GBK * BLD;
    float*         Csm = reinterpret_cast<float*>(smbuf);

    A += (long long)blockIdx.z * sA;
    B += (long long)blockIdx.z * sB;
    C += (long long)blockIdx.z * sC;
    const int m0  = blockIdx.y * GBM;
    const int n0  = blockIdx.x * GBN;
    const int tid = threadIdx.x;
    const int wid = tid >> 5;
    const int wm  = wid >> 1;  // 0..3
    const int wn  = wid & 1;   // 0..1

    wmma::fragment<wmma::accumulator, 16, 16, 16, float> acc[2][2];
    #pragma unroll
    for (int i = 0; i < 2; i++)
        #pragma unroll
        for (int j = 0; j < 2; j++)
            wmma::fill_fragment(acc[i][j], 0.0f);

    for (int kt = 0; kt < K; kt += GBK) {
        // stage A tile 128x32 (split fp32 -> bf16 hi/lo)
        #pragma unroll
        for (int i = 0; i < 4; i++) {
            int idx = tid + i * 256;
            int row = idx >> 3;
            int c4  = (idx & 7) << 2;
            float4 v = *reinterpret_cast<const float4*>(A + (long long)(m0 + row) * K + kt + c4);
            split4(v, &Ahi[row * ALD + c4], &Alo[row * ALD + c4]);
        }
        // stage B tile 32x64
        #pragma unroll
        for (int i = 0; i < 2; i++) {
            int idx = tid + i * 256;
            int row = idx >> 4;
            int c4  = (idx & 15) << 2;
            float4 v = *reinterpret_cast<const float4*>(B + (long long)(kt + row) * N + n0 + c4);
            split4(v, &Bhi[row * BLD + c4], &Blo[row * BLD + c4]);
        }
        __syncthreads();
        #pragma unroll
        for (int ks = 0; ks < 2; ks++) {
            wmma::fragment<wmma::matrix_a, 16, 16, 16, __nv_bfloat16, wmma::row_major> ah[2], al[2];
            wmma::fragment<wmma::matrix_b, 16, 16, 16, __nv_bfloat16, wmma::row_major> bh[2], bl[2];
            #pragma unroll
            for (int r2 = 0; r2 < 2; r2++) {
                wmma::load_matrix_sync(ah[r2], &Ahi[(wm * 32 + r2 * 16) * ALD + ks * 16], ALD);
                wmma::load_matrix_sync(al[r2], &Alo[(wm * 32 + r2 * 16) * ALD + ks * 16], ALD);
            }
            #pragma unroll
            for (int cn = 0; cn < 2; cn++) {
                wmma::load_matrix_sync(bh[cn], &Bhi[(ks * 16) * BLD + wn * 32 + cn * 16], BLD);
                wmma::load_matrix_sync(bl[cn], &Blo[(ks * 16) * BLD + wn * 32 + cn * 16], BLD);
            }
            #pragma unroll
            for (int r2 = 0; r2 < 2; r2++)
                #pragma unroll
                for (int cn = 0; cn < 2; cn++) {
                    wmma::mma_sync(acc[r2][cn], ah[r2], bh[cn], acc[r2][cn]);
                    wmma::mma_sync(acc[r2][cn], ah[r2], bl[cn], acc[r2][cn]);
                    wmma::mma_sync(acc[r2][cn], al[r2], bh[cn], acc[r2][cn]);
                }
        }
        __syncthreads();
    }

    // epilogue via smem roundtrip (fragment layout is opaque)
    #pragma unroll
    for (int r2 = 0; r2 < 2; r2++)
        #pragma unroll
        for (int cn = 0; cn < 2; cn++)
            wmma::store_matrix_sync(&Csm[(wm * 32 + r2 * 16) * CLD + wn * 32 + cn * 16],
                                    acc[r2][cn], CLD, wmma::mem_row_major);
    __syncthreads();

    #pragma unroll
    for (int i = 0; i < 8; i++) {
        int idx = tid + i * 256;
        int row = idx >> 4;
        int c4  = (idx & 15) << 2;
        float4 v = *reinterpret_cast<const float4*>(&Csm[row * CLD + c4]);
        if (bias != nullptr) {
            float4 bv = *reinterpret_cast<const float4*>(bias + n0 + c4);
            v.x += bv.x; v.y += bv.y; v.z += bv.z; v.w += bv.w;
        }
        if (relu) {
            v.x = fmaxf(v.x, 0.f); v.y = fmaxf(v.y, 0.f);
            v.z = fmaxf(v.z, 0.f); v.w = fmaxf(v.w, 0.f);
        }
        *reinterpret_cast<float4*>(C + (long long)(m0 + row) * N + n0 + c4) = v;
    }
}

// ================== scores: raw S = g @ f^T streamed out + online row max/sum ====
static constexpr int SLD = 132;            // fp32, padded (bank spread)
static constexpr int GLD = 72;             // bf16 ld for g/f tiles (64 + 8 skew)
static constexpr int SCORES_SMEM = 4 * 128 * GLD * 2 + 128 * SLD * 4; // 141312 B

__global__ void __launch_bounds__(512)
scores_kernel(const float* __restrict__ g, const float* __restrict__ f,
              float* __restrict__ sraw, float* __restrict__ rowm, float* __restrict__ rowl)
{
    extern __shared__ unsigned char smraw[];
    __nv_bfloat16* Ghi = reinterpret_cast<__nv_bfloat16*>(smraw);
    __nv_bfloat16* Glo = Ghi + 128 * GLD;
    __nv_bfloat16* Fhi = Glo + 128 * GLD;
    __nv_bfloat16* Flo = Fhi + 128 * GLD;
    float*         S   = reinterpret_cast<float*>(Flo + 128 * GLD);

    const int b   = blockIdx.y;
    const int r0  = blockIdx.x * 128;
    const int tid = threadIdx.x;
    const int wid = tid >> 5;
    const int wm  = wid >> 2;  // 0..3
    const int wn  = wid & 3;   // 0..3

    const float* gbase = g + ((long long)b * NTOK + r0) * FGD;
    const float* fbase = f + (long long)b * NTOK * FGD;

    // stage g block [128 x 64] once
    #pragma unroll
    for (int i = 0; i < 4; i++) {
        int idx = tid + i * 512;
        int row = idx >> 4;
        int c4  = (idx & 15) << 2;
        float4 v = *reinterpret_cast<const float4*>(gbase + row * FGD + c4);
        split4(v, &Ghi[row * GLD + c4], &Glo[row * GLD + c4]);
    }

    float m_run = -1e30f, l_run = 0.0f;
    const int srow = tid >> 2;   // 4 threads per row
    const int q    = tid & 3;
    const float* Sscan = &S[srow * SLD + q * 32];

    for (int ci = 0; ci < 32; ci++) {
        __syncthreads();  // protect F/S reuse from previous chunk (also covers G on ci==0)
        #pragma unroll
        for (int i = 0; i < 4; i++) {
            int idx = tid + i * 512;
            int row = idx >> 4;
            int c4  = (idx & 15) << 2;
            float4 v = *reinterpret_cast<const float4*>(fbase + (long long)(ci * 128 + row) * FGD + c4);
            split4(v, &Fhi[row * GLD + c4], &Flo[row * GLD + c4]);
        }
        __syncthreads();

        wmma::fragment<wmma::accumulator, 16, 16, 16, float> acc[2][2];
        #pragma unroll
        for (int i = 0; i < 2; i++)
            #pragma unroll
            for (int j = 0; j < 2; j++)
                wmma::fill_fragment(acc[i][j], 0.0f);

        #pragma unroll
        for (int ks = 0; ks < 4; ks++) {
            wmma::fragment<wmma::matrix_a, 16, 16, 16, __nv_bfloat16, wmma::row_major> ah[2], al[2];
            wmma::fragment<wmma::matrix_b, 16, 16, 16, __nv_bfloat16, wmma::col_major> bh[2], bl[2];
            #pragma unroll
            for (int r2 = 0; r2 < 2; r2++) {
                wmma::load_matrix_sync(ah[r2], &Ghi[(wm * 32 + r2 * 16) * GLD + ks * 16], GLD);
                wmma::load_matrix_sync(al[r2], &Glo[(wm * 32 + r2 * 16) * GLD + ks * 16], GLD);
            }
            #pragma unroll
            for (int cn = 0; cn < 2; cn++) {
                wmma::load_matrix_sync(bh[cn], &Fhi[(wn * 32 + cn * 16) * GLD + ks * 16], GLD);
                wmma::load_matrix_sync(bl[cn], &Flo[(wn * 32 + cn * 16) * GLD + ks * 16], GLD);
            }
            #pragma unroll
            for (int r2 = 0; r2 < 2; r2++)
                #pragma unroll
                for (int cn = 0; cn < 2; cn++) {
                    wmma::mma_sync(acc[r2][cn], ah[r2], bh[cn], acc[r2][cn]);
                    wmma::mma_sync(acc[r2][cn], ah[r2], bl[cn], acc[r2][cn]);
                    wmma::mma_sync(acc[r2][cn], al[r2], bh[cn], acc[r2][cn]);
                }
        }
        #pragma unroll
        for (int r2 = 0; r2 < 2; r2++)
            #pragma unroll
            for (int cn = 0; cn < 2; cn++)
                wmma::store_matrix_sync(&S[(wm * 32 + r2 * 16) * SLD + wn * 32 + cn * 16],
                                        acc[r2][cn], SLD, wmma::mem_row_major);
        __syncthreads();

        // stream raw scores to gmem (coalesced) and update online softmax stats
        size_t gout = (size_t)(b * NTOK + r0) * NTOK + (size_t)ci * 128;
        #pragma unroll
        for (int i = 0; i < 8; i++) {
            int idx = tid + i * 512;
            int row = idx >> 5;
            int c4  = (idx & 31) << 2;
            float4 v = *reinterpret_cast<const float4*>(&S[row * SLD + c4]);
            *reinterpret_cast<float4*>(sraw + gout + (size_t)row * NTOK + c4) = v;
        }
        float vmax = -1e30f;
        #pragma unroll
        for (int j = 0; j < 32; j++) vmax = fmaxf(vmax, Sscan[j]);
        float mn = fmaxf(m_run, vmax);
        float add = 0.0f;
        #pragma unroll
        for (int j = 0; j < 32; j++) add += __expf(Sscan[j] - mn);
        l_run = l_run * __expf(m_run - mn) + add;
        m_run = mn;
    }

    // combine the 4 lanes of each row (lanes l, l^1, l^2, l^3 share a row)
    #pragma unroll
    for (int off = 1; off < 4; off <<= 1) {
        float mo  = __shfl_xor_sync(0xffffffffu, m_run, off);
        float lo2 = __shfl_xor_sync(0xffffffffu, l_run, off);
        float mn  = fmaxf(m_run, mo);
        l_run = l_run * __expf(m_run - mn) + lo2 * __expf(mo - mn);
        m_run = mn;
    }
    if (q == 0) {
        rowm[b * NTOK + r0 + srow] = m_run;
        rowl[b * NTOK + r0 + srow] = l_run;
    }
}

// ================== normalize: beta = exp(s - m_row) / l_row =====================
__global__ void __launch_bounds__(256)
normalize_kernel(float* __restrict__ beta,
                 const float* __restrict__ rowm, const float* __restrict__ rowl)
{
    long long idx = (long long)blockIdx.x * 256 + threadIdx.x;  // float4 index
    if (idx >= (B_ELEMS >> 2)) return;
    int rowg = (int)(idx >> 10);                                // 1024 float4 per row
    float m   = __ldg(rowm + rowg);
    float inv = 1.0f / __ldg(rowl + rowg);
    float4 v = *reinterpret_cast<float4*>(beta + idx * 4);
    v.x = __expf(v.x - m) * inv;
    v.y = __expf(v.y - m) * inv;
    v.z = __expf(v.z - m) * inv;
    v.w = __expf(v.w - m) * inv;
    *reinterpret_cast<float4*>(beta + idx * 4) = v;
}

// ================== launch ========================================================
extern "C" void kernel_launch(void* const* d_in, const int* in_sizes, int n_in,
                              void* d_out, int out_size)
{
    (void)in_sizes; (void)n_in;
    const float* l  = (const float*)d_in[0];
    const float* r  = (const float*)d_in[1];
    const float* Wf = (const float*)d_in[2];
    const float* Wg = (const float*)d_in[3];
    const float* Wh = (const float*)d_in[4];
    const float* Wo = (const float*)d_in[5];
    const float* bf = (const float*)d_in[6];
    const float* bg = (const float*)d_in[7];
    const float* bh = (const float*)d_in[8];
    const float* bo = (const float*)d_in[9];
    float* out = (float*)d_out;

    float *p_f, *p_g, *p_h, *p_oatt, *p_rowm, *p_rowl, *p_bscr;
    cudaGetSymbolAddress((void**)&p_f,    d_f);
    cudaGetSymbolAddress((void**)&p_g,    d_g);
    cudaGetSymbolAddress((void**)&p_h,    d_h);
    cudaGetSymbolAddress((void**)&p_oatt, d_oatt);
    cudaGetSymbolAddress((void**)&p_rowm, d_rowm);
    cudaGetSymbolAddress((void**)&p_rowl, d_rowl);
    cudaGetSymbolAddress((void**)&p_bscr, d_beta_scratch);

    // output layout: reference returns (o, beta) -> o first, then beta
    float* o_out    = nullptr;
    float* beta_out = nullptr;
    long long osz = (long long)out_size;
    if (osz >= O_ELEMS + B_ELEMS) { o_out = out; beta_out = out + O_ELEMS; }
    else if (osz == B_ELEMS)      { beta_out = out; }
    else                          { o_out = out; beta_out = p_bscr; }

    cudaFuncSetAttribute(scores_kernel, cudaFuncAttributeMaxDynamicSharedMemorySize, SCORES_SMEM);

    // f = relu(l @ Wf + bf)   [16384, 64]
    gemm_split_kernel<<<dim3(1, 128, 1), 256>>>(l, Wf, bf, p_f, 512, 64, 0, 0, 0, 1);
    // g = relu(r @ Wg + bg)   [16384, 64]
    gemm_split_kernel<<<dim3(1, 128, 1), 256>>>(r, Wg, bg, p_g, 512, 64, 0, 0, 0, 1);
    // h = relu(l @ Wh + bh)   [16384, 512]
    gemm_split_kernel<<<dim3(8, 128, 1), 256>>>(l, Wh, bh, p_h, 512, 512, 0, 0, 0, 1);
    // raw scores + row max / sumexp
    scores_kernel<<<dim3(32, 4, 1), 512, SCORES_SMEM>>>(p_g, p_f, beta_out, p_rowm, p_rowl);
    // beta = softmax(s)
    normalize_kernel<<<65536, 256>>>(beta_out, p_rowm, p_rowl);
    if (o_out) {
        // o_att = beta @ h  (per batch)
        gemm_split_kernel<<<dim3(8, 32, 4), 256>>>(beta_out, p_h, nullptr, p_oatt,
                                                   4096, 512,
                                                   (long long)NTOK * NTOK,
                                                   (long long)NTOK * CH,
                                                   (long long)NTOK * CH, 0);
        // o = relu(o_att @ Wo + bo)   [16384, 512]
        gemm_split_kernel<<<dim3(8, 128, 1), 256>>>(p_oatt, Wo, bo, o_out, 512, 512, 0, 0, 0, 1);
    }
}